// round 4
// baseline (speedup 1.0000x reference)
#include <cuda_runtime.h>
#include <math.h>

// Problem constants (sizes also derived from in_sizes at launch)
#define NMAX 50000
#define EMAX 800000

// ---------------- scratch (static device globals; referenced directly in kernels)
__device__ float g_xlr1[(size_t)NMAX * 512];   // [xl1 | xr1] per node, 256+256
__device__ float g_h1[(size_t)NMAX * 256];     // layer-1 output
__device__ float g_xlr2[(size_t)NMAX * 128];   // [xl2 | xr2] per node, 64+64
__device__ float g_scores[(size_t)EMAX * 4];   // per-edge scores (layer1: E*4, layer2 reuses E*1)
__device__ int   g_src32[EMAX];
__device__ int   g_dst32[EMAX];
__device__ int   g_deg[NMAX];
__device__ int   g_cursor[NMAX];
__device__ int   g_offs[NMAX + 1];
__device__ int   g_srcs[EMAX];                 // CSR-sorted source ids (by dst)
__device__ int   g_is_i32;                     // dtype flag: nonzero -> int32 edge_index

// ---------------------------------------------------------------------------
__global__ void zero2_k(int n) {
    int i = blockIdx.x * blockDim.x + threadIdx.x;
    if (i < n) { g_deg[i] = 0; g_cursor[i] = 0; }
    if (i == 0) g_is_i32 = 0;
}

// Detect dtype: under int64 interpretation, odd 32-bit words of the first E
// elements are the high halves of non-negative ids < 2^31 -> all zero.
// Under int32, those words are random node ids -> some nonzero.
__global__ void detect_k(const unsigned int* __restrict__ w, int E) {
    int i = blockIdx.x * blockDim.x + threadIdx.x;
    if (i < E && w[2 * i + 1] != 0u) atomicOr(&g_is_i32, 1);
}

__global__ void convert_k(const void* __restrict__ ei, int E, int N) {
    int e = blockIdx.x * blockDim.x + threadIdx.x;
    if (e >= E) return;
    int s, d;
    if (g_is_i32) {
        const int* p = (const int*)ei;
        s = p[e];
        d = p[E + e];
    } else {
        const long long* p = (const long long*)ei;
        s = (int)p[e];
        d = (int)p[E + e];
    }
    // clamp: a mis-detected dtype degrades to wrong values, never OOB
    s = min(max(s, 0), N - 1);
    d = min(max(d, 0), N - 1);
    g_src32[e] = s;
    g_dst32[e] = d;
}

__global__ void hist_k(int E) {
    int e = blockIdx.x * blockDim.x + threadIdx.x;
    if (e < E) atomicAdd(&g_deg[g_dst32[e]], 1);
}

// single-block exclusive scan over n (~50k) elements, g_offs[n] = total
__global__ void scan_k(int n) {
    __shared__ int buf[1024];
    int tid = threadIdx.x;
    int per = (n + 1023) >> 10;
    int start = tid * per;
    int end = min(start + per, n);
    int s = 0;
    for (int i = start; i < end; i++) s += g_deg[i];
    buf[tid] = s;
    __syncthreads();
    for (int off = 1; off < 1024; off <<= 1) {
        int v = (tid >= off) ? buf[tid - off] : 0;
        __syncthreads();
        buf[tid] += v;
        __syncthreads();
    }
    int base = tid ? buf[tid - 1] : 0;
    for (int i = start; i < end; i++) { g_offs[i] = base; base += g_deg[i]; }
    if (tid == 1023) g_offs[n] = buf[1023];
}

__global__ void scatter_k(int E) {
    int e = blockIdx.x * blockDim.x + threadIdx.x;
    if (e >= E) return;
    int d = g_dst32[e];
    int pos = g_offs[d] + atomicAdd(&g_cursor[d], 1);
    g_srcs[pos] = g_src32[e];
}

// ---------------------------------------------------------------------------
// Dual-B SGEMM body: C[M, 2H] = A[M,K] @ [Bl | Br]  (Bl,Br are [K,H] row-major)
// 64x64 tiles, TK=16, 256 threads, 4x4 microtile.
#define GTM 64
#define GTN 64
#define GTK 16
__device__ __forceinline__ void gemm_body(
    const float* __restrict__ A, const float* __restrict__ Bl, const float* __restrict__ Br,
    float* __restrict__ C, int M, int K, int H)
{
    __shared__ float As[GTK][GTM];       // As[k][m]
    __shared__ float Bs[GTK][GTN + 4];   // Bs[k][n]
    int row0 = blockIdx.y * GTM, col0 = blockIdx.x * GTN;
    const float* B; int c0;
    if (col0 < H) { B = Bl; c0 = col0; } else { B = Br; c0 = col0 - H; }
    int tid = threadIdx.x;
    int tx = tid & 15, ty = tid >> 4;
    int am = tid >> 2, ak = (tid & 3) * 4;   // A loader: row am (0..63), k quad
    int kb = tid >> 4, bn = (tid & 15) * 4;  // B loader: k row kb (0..15), col quad
    int NC = 2 * H;
    float acc[4][4] = {};
    for (int k0 = 0; k0 < K; k0 += GTK) {
        float4 av = make_float4(0.f, 0.f, 0.f, 0.f);
        int ar = row0 + am;
        if (ar < M) av = *(const float4*)&A[(size_t)ar * K + k0 + ak];
        As[ak + 0][am] = av.x; As[ak + 1][am] = av.y;
        As[ak + 2][am] = av.z; As[ak + 3][am] = av.w;
        float4 bv = *(const float4*)&B[(size_t)(k0 + kb) * H + c0 + bn];
        Bs[kb][bn + 0] = bv.x; Bs[kb][bn + 1] = bv.y;
        Bs[kb][bn + 2] = bv.z; Bs[kb][bn + 3] = bv.w;
        __syncthreads();
#pragma unroll
        for (int k = 0; k < GTK; k++) {
            float a0 = As[k][ty * 4 + 0], a1 = As[k][ty * 4 + 1];
            float a2 = As[k][ty * 4 + 2], a3 = As[k][ty * 4 + 3];
            float b0 = Bs[k][tx * 4 + 0], b1 = Bs[k][tx * 4 + 1];
            float b2 = Bs[k][tx * 4 + 2], b3 = Bs[k][tx * 4 + 3];
            acc[0][0] += a0 * b0; acc[0][1] += a0 * b1; acc[0][2] += a0 * b2; acc[0][3] += a0 * b3;
            acc[1][0] += a1 * b0; acc[1][1] += a1 * b1; acc[1][2] += a1 * b2; acc[1][3] += a1 * b3;
            acc[2][0] += a2 * b0; acc[2][1] += a2 * b1; acc[2][2] += a2 * b2; acc[2][3] += a2 * b3;
            acc[3][0] += a3 * b0; acc[3][1] += a3 * b1; acc[3][2] += a3 * b2; acc[3][3] += a3 * b3;
        }
        __syncthreads();
    }
#pragma unroll
    for (int i = 0; i < 4; i++) {
        int r = row0 + ty * 4 + i;
        if (r < M) {
            float4 v = make_float4(acc[i][0], acc[i][1], acc[i][2], acc[i][3]);
            *(float4*)&C[(size_t)r * NC + col0 + tx * 4] = v;
        }
    }
}

__global__ void __launch_bounds__(256) gemm1_wrap(
    const float* __restrict__ A, const float* __restrict__ Bl, const float* __restrict__ Br,
    int M, int K, int H)
{
    gemm_body(A, Bl, Br, g_xlr1, M, K, H);
}

__global__ void __launch_bounds__(256) gemm2_wrap(
    const float* __restrict__ Bl, const float* __restrict__ Br,
    int M, int K, int H)
{
    gemm_body(g_h1, Bl, Br, g_xlr2, M, K, H);
}

// ---------------------------------------------------------------------------
__device__ __forceinline__ float elu1(float v) { return v > 0.f ? v : expm1f(v); }

// Layer-1 GATv2 node kernel: one warp per destination node.
// lane handles 8 contiguous dims (d = lane*8); head = lane>>3 (8 lanes/head).
__global__ void __launch_bounds__(256) layer1_node(
    const float* __restrict__ att, const float* __restrict__ bias, int n_nodes)
{
    int warp = (blockIdx.x * blockDim.x + threadIdx.x) >> 5;
    if (warp >= n_nodes) return;
    int lane = threadIdx.x & 31;
    int sub = lane & 7;
    int h = lane >> 3;
    int d = lane * 8;  // == h*64 + sub*8

    const float4* xrp = (const float4*)&g_xlr1[(size_t)warp * 512 + 256 + d];
    float4 xr0 = xrp[0], xr1 = xrp[1];
    const float4* ap = (const float4*)&att[d];
    float4 a0 = ap[0], a1 = ap[1];

    int r0 = g_offs[warp], r1 = g_offs[warp + 1];
    float mx = -INFINITY;
    for (int p = r0; p < r1; p++) {
        int s = g_srcs[p];
        const float4* xp = (const float4*)&g_xlr1[(size_t)s * 512 + d];
        float4 x0 = xp[0], x1 = xp[1];
        float t, part;
        t = x0.x + xr0.x; t = fmaxf(t, 0.2f * t); part  = t * a0.x;
        t = x0.y + xr0.y; t = fmaxf(t, 0.2f * t); part += t * a0.y;
        t = x0.z + xr0.z; t = fmaxf(t, 0.2f * t); part += t * a0.z;
        t = x0.w + xr0.w; t = fmaxf(t, 0.2f * t); part += t * a0.w;
        t = x1.x + xr1.x; t = fmaxf(t, 0.2f * t); part += t * a1.x;
        t = x1.y + xr1.y; t = fmaxf(t, 0.2f * t); part += t * a1.y;
        t = x1.z + xr1.z; t = fmaxf(t, 0.2f * t); part += t * a1.z;
        t = x1.w + xr1.w; t = fmaxf(t, 0.2f * t); part += t * a1.w;
        part += __shfl_xor_sync(0xffffffffu, part, 1);
        part += __shfl_xor_sync(0xffffffffu, part, 2);
        part += __shfl_xor_sync(0xffffffffu, part, 4);
        if (sub == 0) g_scores[(size_t)p * 4 + h] = part;
        mx = fmaxf(mx, part);
    }
    float ac0 = 0, ac1 = 0, ac2 = 0, ac3 = 0, ac4 = 0, ac5 = 0, ac6 = 0, ac7 = 0, den = 0;
    for (int p = r0; p < r1; p++) {
        int s = g_srcs[p];
        float sc = g_scores[(size_t)p * 4 + h];
        float w = __expf(sc - mx);
        den += w;
        const float4* xp = (const float4*)&g_xlr1[(size_t)s * 512 + d];
        float4 x0 = xp[0], x1 = xp[1];
        ac0 += w * x0.x; ac1 += w * x0.y; ac2 += w * x0.z; ac3 += w * x0.w;
        ac4 += w * x1.x; ac5 += w * x1.y; ac6 += w * x1.z; ac7 += w * x1.w;
    }
    float inv = (den > 0.f) ? 1.f / den : 0.f;
    const float4* bp = (const float4*)&bias[d];
    float4 b0v = bp[0], b1v = bp[1];
    float4 o0, o1;
    o0.x = elu1(ac0 * inv + b0v.x); o0.y = elu1(ac1 * inv + b0v.y);
    o0.z = elu1(ac2 * inv + b0v.z); o0.w = elu1(ac3 * inv + b0v.w);
    o1.x = elu1(ac4 * inv + b1v.x); o1.y = elu1(ac5 * inv + b1v.y);
    o1.z = elu1(ac6 * inv + b1v.z); o1.w = elu1(ac7 * inv + b1v.w);
    float4* op = (float4*)&g_h1[(size_t)warp * 256 + d];
    op[0] = o0; op[1] = o1;
}

// Layer-2 GATv2 (heads=1, hid=64) + fused final linear [64,2] + bias -> out
__global__ void __launch_bounds__(256) layer2_node(
    const float* __restrict__ att, const float* __restrict__ bias,
    const float* __restrict__ Wlin, const float* __restrict__ blin,
    float* __restrict__ out, int n_nodes)
{
    int warp = (blockIdx.x * blockDim.x + threadIdx.x) >> 5;
    if (warp >= n_nodes) return;
    int lane = threadIdx.x & 31;
    int d = lane * 2;

    float2 xr = *(const float2*)&g_xlr2[(size_t)warp * 128 + 64 + d];
    float2 av = *(const float2*)&att[d];
    int r0 = g_offs[warp], r1 = g_offs[warp + 1];
    float mx = -INFINITY;
    for (int p = r0; p < r1; p++) {
        int s = g_srcs[p];
        float2 xl = *(const float2*)&g_xlr2[(size_t)s * 128 + d];
        float t, part;
        t = xl.x + xr.x; t = fmaxf(t, 0.2f * t); part  = t * av.x;
        t = xl.y + xr.y; t = fmaxf(t, 0.2f * t); part += t * av.y;
#pragma unroll
        for (int off = 16; off; off >>= 1) part += __shfl_xor_sync(0xffffffffu, part, off);
        if (lane == 0) g_scores[p] = part;
        mx = fmaxf(mx, part);
    }
    float a0 = 0, a1 = 0, den = 0;
    for (int p = r0; p < r1; p++) {
        int s = g_srcs[p];
        float w = __expf(g_scores[p] - mx);
        den += w;
        float2 xl = *(const float2*)&g_xlr2[(size_t)s * 128 + d];
        a0 += w * xl.x; a1 += w * xl.y;
    }
    float inv = (den > 0.f) ? 1.f / den : 0.f;
    float h0 = elu1(a0 * inv + bias[d]);
    float h1 = elu1(a1 * inv + bias[d + 1]);
    float o0 = h0 * Wlin[d * 2 + 0] + h1 * Wlin[d * 2 + 2];
    float o1 = h0 * Wlin[d * 2 + 1] + h1 * Wlin[d * 2 + 3];
#pragma unroll
    for (int off = 16; off; off >>= 1) {
        o0 += __shfl_xor_sync(0xffffffffu, o0, off);
        o1 += __shfl_xor_sync(0xffffffffu, o1, off);
    }
    if (lane == 0) {
        out[(size_t)warp * 2 + 0] = o0 + blin[0];
        out[(size_t)warp * 2 + 1] = o1 + blin[1];
    }
}

// ---------------------------------------------------------------------------
extern "C" void kernel_launch(void* const* d_in, const int* in_sizes, int n_in,
                              void* d_out, int out_size)
{
    const float* x    = (const float*)d_in[0];
    const void*  ei   = d_in[1];                 // [2,E], int32 or int64
    const float* W1l  = (const float*)d_in[2];
    const float* W1r  = (const float*)d_in[3];
    const float* att1 = (const float*)d_in[4];
    const float* b1   = (const float*)d_in[5];
    const float* W2l  = (const float*)d_in[6];
    const float* W2r  = (const float*)d_in[7];
    const float* att2 = (const float*)d_in[8];
    const float* b2   = (const float*)d_in[9];
    const float* Wlin = (const float*)d_in[10];
    const float* blin = (const float*)d_in[11];
    float* out = (float*)d_out;

    int N = in_sizes[0] / 128;
    int E = in_sizes[1] / 2;

    // ---- edge_index dtype detect + canonicalize to int32 ----
    zero2_k<<<(N + 255) / 256, 256>>>(N);
    detect_k<<<(E + 255) / 256, 256>>>((const unsigned int*)ei, E);
    convert_k<<<(E + 255) / 256, 256>>>(ei, E, N);

    // ---- CSR build (by destination) ----
    hist_k<<<(E + 255) / 256, 256>>>(E);
    scan_k<<<1, 1024>>>(N);
    scatter_k<<<(E + 255) / 256, 256>>>(E);

    // ---- layer 1 ----
    {
        dim3 grid(512 / GTN, (N + GTM - 1) / GTM);
        gemm1_wrap<<<grid, 256>>>(x, W1l, W1r, N, 128, 256);
    }
    layer1_node<<<(N + 7) / 8, 256>>>(att1, b1, N);

    // ---- layer 2 + fused final linear ----
    {
        dim3 grid(128 / GTN, (N + GTM - 1) / GTM);
        gemm2_wrap<<<grid, 256>>>(W2l, W2r, N, 256, 64);
    }
    layer2_node<<<(N + 7) / 8, 256>>>(att2, b2, Wlin, blin, out, N);
}